// round 16
// baseline (speedup 1.0000x reference)
#include <cuda_runtime.h>
#include <cuda_fp16.h>
#include <cstdint>
#include <cstddef>

// ============================================================================
// Problem constants
// ============================================================================
#define HDIM 4096
#define BDIM 4096
static constexpr size_t BH_ = (size_t)HDIM * (size_t)BDIM;   // 16777216

// ============================================================================
// Device scratch (__device__ globals; allocation is forbidden).
//   g_act slots: 0=xk 1=xv 2=xr 3=g(r*wkv)     (fp16, [B,H] K-major)
//   g_wt  slots: 0=Wk^T 1=Wv^T 2=Wr^T 3=Wo^T   (fp16, [N,K] K-major)
//   g_lin slots: 0=k 1=v 2=r_linear            (fp32 [B,H])
// ============================================================================
__device__ __align__(128) __half g_act[4 * BH_];
__device__ __align__(128) __half g_wt[4 * BH_];
__device__ __align__(128) float  g_lin[3 * BH_];

__device__ __forceinline__ uint32_t smem_u32(const void* p) {
    uint32_t a;
    asm("{ .reg .u64 t; cvta.to.shared.u64 t, %1; cvt.u32.u64 %0, t; }"
        : "=r"(a) : "l"(p));
    return a;
}

#define SWZ(o) ((o) ^ (((o) >> 3) & 0x70))

// A loads: .ca (L1-cached) — co-resident CTAs (adjacent bidlin, 16-wide
// n-swizzle) share the same A row-panel, so the second CTA hits L1.
#define CP_ASYNC16_CA(sa, ga)                                                  \
    asm volatile("cp.async.ca.shared.global [%0], [%1], 16;"                   \
                 :: "r"(sa), "l"(ga))
// B loads: .cg (L1-bypass) — B panels are not shared between co-residents.
#define CP_ASYNC16_CG(sa, ga)                                                  \
    asm volatile("cp.async.cg.shared.global [%0], [%1], 16;"                   \
                 :: "r"(sa), "l"(ga))

#define MBAR_INIT(addr, cnt)                                                   \
    asm volatile("mbarrier.init.shared.b64 [%0], %1;"                          \
                 :: "r"(addr), "r"(cnt) : "memory")
#define MBAR_ARRIVE(addr)                                                      \
    asm volatile("mbarrier.arrive.shared.b64 _, [%0];"                         \
                 :: "r"(addr) : "memory")
#define CPASYNC_MBAR_ARRIVE(addr)                                              \
    asm volatile("cp.async.mbarrier.arrive.noinc.shared.b64 [%0];"             \
                 :: "r"(addr) : "memory")

#define MBAR_WAIT(addr, ph) do {                                               \
    uint32_t _m = (uint32_t)(addr), _p = (uint32_t)(ph), _d;                   \
    asm volatile(                                                              \
        "{\n\t.reg .pred p;\n\t"                                               \
        "mbarrier.try_wait.parity.acquire.cta.shared::cta.b64 p, [%1], %2;\n\t"\
        "selp.b32 %0, 1, 0, p;\n\t}"                                           \
        : "=r"(_d) : "r"(_m), "r"(_p) : "memory");                             \
    if (!_d) {                                                                 \
        asm volatile(                                                          \
            "{\n\t.reg .pred P1;\n\t"                                          \
            "WL%=:\n\t"                                                        \
            "mbarrier.try_wait.parity.acquire.cta.shared::cta.b64 P1, [%0], %1, 0x989680;\n\t" \
            "@P1 bra.uni WD%=;\n\t"                                            \
            "bra.uni WL%=;\n\t"                                                \
            "WD%=:\n\t}"                                                       \
            :: "r"(_m), "r"(_p) : "memory");                                   \
    }                                                                          \
} while (0)

#define LDSM_X4(r0, r1, r2, r3, addr)                                          \
    asm volatile("ldmatrix.sync.aligned.m8n8.x4.shared.b16 {%0,%1,%2,%3}, [%4];" \
                 : "=r"(r0), "=r"(r1), "=r"(r2), "=r"(r3) : "r"(addr))

#define MMA16816(c, a, b0, b1)                                                 \
    asm volatile("mma.sync.aligned.m16n8k16.row.col.f32.f16.f16.f32 "          \
                 "{%0,%1,%2,%3}, {%4,%5,%6,%7}, {%8,%9}, {%0,%1,%2,%3};"       \
                 : "+f"((c)[0]), "+f"((c)[1]), "+f"((c)[2]), "+f"((c)[3])      \
                 : "r"((a)[0]), "r"((a)[1]), "r"((a)[2]), "r"((a)[3]),         \
                   "r"(b0), "r"(b1))

// ============================================================================
// HGEMM (r7 pipeline — measured best): C[M,N] = A[M,K] @ B^T.
// CTA tile 128x128, BK=64, 3-slot mbarrier ring, 4 warps 64x64, occ 2.
// ============================================================================
#define BM 128
#define BN 128
#define BK 64
#define GTHREADS 128
#define NKITERS (HDIM / BK)                 // 64
#define STAGE_BYTES ((BM + BN) * 128)       // 32768
#define SM_B_OFF (BM * 128)                 // 16384
#define SM_TILE0 1024
#define GSMEM (SM_TILE0 + 3 * STAGE_BYTES)  // 99328

__global__ void __launch_bounds__(GTHREADS, 2)
hgemm_kernel(float* __restrict__ Cout, int mode)
{
    extern __shared__ char smem[];
    const uint32_t sb = smem_u32(smem);
    const int tid = threadIdx.x;
    const int wid = tid >> 5;
    const int lane = tid & 31;

    const int z = (mode == 0) ? (int)blockIdx.z : 3;
    const __half* __restrict__ A = g_act + (size_t)z * BH_;
    const __half* __restrict__ Bw = g_wt + (size_t)z * BH_;
    float* __restrict__ C = (mode == 0) ? (g_lin + (size_t)z * BH_) : Cout;

    // ---- CTA swizzle: 16-wide x-groups (adjacent CTAs share A panel) ----
    const int bidlin = (int)(blockIdx.x + gridDim.x * blockIdx.y);
    const int per = 16 * (int)gridDim.y;
    const int grp = bidlin / per;
    const int rem = bidlin - grp * per;
    const int m0 = (rem / 16) * BM;
    const int n0 = (grp * 16 + (rem % 16)) * BN;

    // ---- mbarrier init: full[s] at sb+16s, empty[s] at sb+16s+8 ----
    if (tid == 0) {
        #pragma unroll
        for (int s = 0; s < 3; s++) {
            MBAR_INIT(sb + s * 16, GTHREADS);
            MBAR_INIT(sb + s * 16 + 8, GTHREADS);
        }
    }
    __syncthreads();

    // ---- cp.async bases ----
    const int lrow = tid >> 3, lcol = tid & 7;
    const __half* gAb = A + (size_t)(m0 + lrow) * HDIM + lcol * 8;
    const __half* gBb = Bw + (size_t)(n0 + lrow) * HDIM + lcol * 8;
    const uint32_t soff = SWZ((uint32_t)(lrow * 128 + lcol * 16));
    const uint32_t sAb = sb + SM_TILE0 + soff;
    const uint32_t sBb = sb + SM_TILE0 + SM_B_OFF + soff;

    #define LOAD_STAGE(slot, kc) do {                                          \
        uint32_t off = (uint32_t)(slot) * STAGE_BYTES;                         \
        size_t ko = (size_t)(kc) * BK;                                         \
        _Pragma("unroll")                                                      \
        for (int c = 0; c < 8; c++)                                            \
            CP_ASYNC16_CA(sAb + off + c * 2048, gAb + ko + (size_t)c * 16 * HDIM);\
        _Pragma("unroll")                                                      \
        for (int c = 0; c < 8; c++)                                            \
            CP_ASYNC16_CG(sBb + off + c * 2048, gBb + ko + (size_t)c * 16 * HDIM);\
    } while (0)

    // ---- warp tiling: 2x2 warps, each 64x64 ----
    const int wm = (wid & 1) * 64;
    const int wn = (wid >> 1) * 64;
    const uint32_t xorv = (uint32_t)((lane & 7) << 4);
    const uint32_t bcol0 = (uint32_t)((lane >> 4) << 4);
    uint32_t rowAoff[4], rowBoff[4];
    #pragma unroll
    for (int mt = 0; mt < 4; mt++)
        rowAoff[mt] = (uint32_t)(SM_TILE0 + (wm + (lane & 15) + mt * 16) * 128);
    #pragma unroll
    for (int nt2 = 0; nt2 < 4; nt2++)
        rowBoff[nt2] = (uint32_t)(SM_TILE0 + SM_B_OFF + (wn + nt2 * 16 + (lane & 15)) * 128);

    float acc[4][8][4];
    #pragma unroll
    for (int mt = 0; mt < 4; mt++)
        #pragma unroll
        for (int nt = 0; nt < 8; nt++)
            #pragma unroll
            for (int e = 0; e < 4; e++) acc[mt][nt][e] = 0.0f;

    uint32_t af[2][4][4], bf[2][4][4];
    #define LOADFRAG(buf, sbase_, ks_) do {                                    \
        const uint32_t bc = ((uint32_t)((ks_) * 32) + bcol0) ^ xorv;           \
        _Pragma("unroll")                                                      \
        for (int mt = 0; mt < 4; mt++)                                         \
            LDSM_X4(af[buf][mt][0], af[buf][mt][1], af[buf][mt][2],            \
                    af[buf][mt][3], (sbase_) + rowAoff[mt] + bc);              \
        _Pragma("unroll")                                                      \
        for (int nt2 = 0; nt2 < 4; nt2++)                                      \
            LDSM_X4(bf[buf][nt2][0], bf[buf][nt2][1], bf[buf][nt2][2],         \
                    bf[buf][nt2][3], (sbase_) + rowBoff[nt2] + bc);            \
    } while (0)

    // ---- prologue: stages 0 and 1 ----
    LOAD_STAGE(0, 0);
    CPASYNC_MBAR_ARRIVE(sb + 0 * 16);
    LOAD_STAGE(1, 1);
    CPASYNC_MBAR_ARRIVE(sb + 1 * 16);

    for (int kc = 0; kc < NKITERS; kc++) {
        const int s = kc - (kc / 3) * 3;
        const int t = kc + 2;
        if (t < NKITERS) {
            const int s2 = t - (t / 3) * 3;
            if (t >= 3)
                MBAR_WAIT(sb + s2 * 16 + 8, ((t - 3) / 3) & 1);
            LOAD_STAGE(s2, t);
            CPASYNC_MBAR_ARRIVE(sb + s2 * 16);
        }
        MBAR_WAIT(sb + s * 16, (kc / 3) & 1);

        const uint32_t sbase = sb + (uint32_t)s * STAGE_BYTES;
        LOADFRAG(0, sbase, 0);
        #pragma unroll
        for (int ks = 0; ks < 4; ks++) {
            const int cur = ks & 1;
            if (ks < 3) LOADFRAG(cur ^ 1, sbase, ks + 1);
            #pragma unroll
            for (int mt = 0; mt < 4; mt++) {
                #pragma unroll
                for (int nt = 0; nt < 8; nt++) {
                    uint32_t b0 = (nt & 1) ? bf[cur][nt >> 1][1] : bf[cur][nt >> 1][0];
                    uint32_t b1 = (nt & 1) ? bf[cur][nt >> 1][3] : bf[cur][nt >> 1][2];
                    MMA16816(acc[mt][nt], af[cur][mt], b0, b1);
                }
            }
        }
        MBAR_ARRIVE(sb + s * 16 + 8);
    }

    // ---- epilogue ----
    const int gr = lane >> 2;
    const int gc = (lane & 3) * 2;
    #pragma unroll
    for (int mt = 0; mt < 4; mt++) {
        #pragma unroll
        for (int nt = 0; nt < 8; nt++) {
            int row = m0 + wm + mt * 16 + gr;
            int col = n0 + wn + nt * 8 + gc;
            float2 v0 = make_float2(acc[mt][nt][0], acc[mt][nt][1]);
            float2 v1 = make_float2(acc[mt][nt][2], acc[mt][nt][3]);
            *(float2*)(C + (size_t)row * HDIM + col) = v0;
            *(float2*)(C + (size_t)(row + 8) * HDIM + col) = v1;
        }
    }
    #undef LOAD_STAGE
    #undef LOADFRAG
}

// ============================================================================
// Fused prep kernel: weight transpose+fp16 convert AND token-shift mixing.
// ============================================================================
#define WSPLIT_BLOCKS (4 * (HDIM / 32) * (HDIM / 32))   // 65536
#define MIX_BLOCKS ((int)(BH_ / 4 / 256))               // 16384

__device__ __forceinline__ void half_store4(int slot, size_t i,
                                            float a0, float a1, float a2, float a3)
{
    union { __half h[4]; uint2 u; } u;
    u.h[0] = __float2half_rn(a0);
    u.h[1] = __float2half_rn(a1);
    u.h[2] = __float2half_rn(a2);
    u.h[3] = __float2half_rn(a3);
    ((uint2*)g_act)[(size_t)slot * (BH_ / 4) + i] = u.u;
}

__global__ void prep_kernel(const float* __restrict__ W0, const float* __restrict__ W1,
                            const float* __restrict__ W2, const float* __restrict__ W3,
                            const float4* __restrict__ x, const float4* __restrict__ sx,
                            const float* __restrict__ km, const float* __restrict__ vm,
                            const float* __restrict__ rm, float4* __restrict__ out_x,
                            int do_copy)
{
    __shared__ float tile[32][33];
    int b = (int)blockIdx.x;
    if (b < WSPLIT_BLOCKS) {
        const int z = b >> 14;                   // / (128*128)
        const int r = b & 16383;
        const int n0 = (r & 127) * 32;
        const int k0 = (r >> 7) * 32;
        const float* W = (z == 0) ? W0 : (z == 1) ? W1 : (z == 2) ? W2 : W3;
        const int tx = threadIdx.x & 31, ty = threadIdx.x >> 5;   // 32 x 8

        #pragma unroll
        for (int i = 0; i < 4; i++)
            tile[ty + 8 * i][tx] = W[(size_t)(k0 + ty + 8 * i) * HDIM + (n0 + tx)];
        __syncthreads();

        const size_t base = (size_t)z * BH_;
        #pragma unroll
        for (int i = 0; i < 4; i++) {
            float v = tile[tx][ty + 8 * i];
            g_wt[base + (size_t)(n0 + ty + 8 * i) * HDIM + (k0 + tx)] = __float2half_rn(v);
        }
    } else {
        b -= WSPLIT_BLOCKS;
        size_t i = (size_t)b * 256 + threadIdx.x;    // over BH/4
        float4 xv = x[i], sv = sx[i];
        int h = (int)((i * 4) & (HDIM - 1));
        float4 kmv = *(const float4*)(km + h);
        float4 vmv = *(const float4*)(vm + h);
        float4 rmv = *(const float4*)(rm + h);
        if (do_copy) out_x[i] = xv;
        half_store4(0, i,
            fmaf(kmv.x, xv.x - sv.x, sv.x), fmaf(kmv.y, xv.y - sv.y, sv.y),
            fmaf(kmv.z, xv.z - sv.z, sv.z), fmaf(kmv.w, xv.w - sv.w, sv.w));
        half_store4(1, i,
            fmaf(vmv.x, xv.x - sv.x, sv.x), fmaf(vmv.y, xv.y - sv.y, sv.y),
            fmaf(vmv.z, xv.z - sv.z, sv.z), fmaf(vmv.w, xv.w - sv.w, sv.w));
        half_store4(2, i,
            fmaf(rmv.x, xv.x - sv.x, sv.x), fmaf(rmv.y, xv.y - sv.y, sv.y),
            fmaf(rmv.z, xv.z - sv.z, sv.z), fmaf(rmv.w, xv.w - sv.w, sv.w));
    }
}

// ============================================================================
// WKV elementwise
// ============================================================================
__device__ __forceinline__ void wkv_comp(float k, float v, float rl,
                                         float A, float Bv, float P,
                                         float tfv, float tdv,
                                         float& aa, float& bb, float& p2o, float& g)
{
    float r = 1.0f / (1.0f + expf(-rl));
    float w = k + tfv;
    float p = fmaxf(P, w);
    float e1 = expf(P - p), e2 = expf(w - p);
    float wkv = (e1 * A + e2 * v) / (e1 * Bv + e2);
    float w2 = P + tdv;
    p2o = fmaxf(w2, k);
    float ea = expf(w2 - p2o), eb = expf(k - p2o);
    aa = ea * A + eb * v;
    bb = ea * Bv + eb;
    g = r * wkv;
}

__global__ void wkv_kernel(const float4* __restrict__ sa, const float4* __restrict__ sb,
                           const float4* __restrict__ sp, const float* __restrict__ td,
                           const float* __restrict__ tf, float* __restrict__ out,
                           int nslots)
{
    size_t i = (size_t)blockIdx.x * blockDim.x + threadIdx.x;    // over BH/4
    int h = (int)((i * 4) & (HDIM - 1));
    const float4* lin = (const float4*)g_lin;
    float4 k4 = lin[i];
    float4 v4 = lin[BH_ / 4 + i];
    float4 r4 = lin[2 * (BH_ / 4) + i];
    float4 sa4 = sa[i], sb4 = sb[i], sp4 = sp[i];
    float4 tf4 = *(const float4*)(tf + h);
    float4 td4 = *(const float4*)(td + h);

    float4 aa4, bb4, p24;
    float g0, g1, g2, g3;
    wkv_comp(k4.x, v4.x, r4.x, sa4.x, sb4.x, sp4.x, tf4.x, td4.x, aa4.x, bb4.x, p24.x, g0);
    wkv_comp(k4.y, v4.y, r4.y, sa4.y, sb4.y, sp4.y, tf4.y, td4.y, aa4.y, bb4.y, p24.y, g1);
    wkv_comp(k4.z, v4.z, r4.z, sa4.z, sb4.z, sp4.z, tf4.z, td4.z, aa4.z, bb4.z, p24.z, g2);
    wkv_comp(k4.w, v4.w, r4.w, sa4.w, sb4.w, sp4.w, tf4.w, td4.w, aa4.w, bb4.w, p24.w, g3);

    if (nslots > 2) ((float4*)(out + 2 * BH_))[i] = aa4;
    if (nslots > 3) ((float4*)(out + 3 * BH_))[i] = bb4;
    if (nslots > 4) ((float4*)(out + 4 * BH_))[i] = p24;
    half_store4(3, i, g0, g1, g2, g3);
}

// ============================================================================
// Launch (serial r7 schedule — co-tenancy with the GEMM measurably loses)
// ============================================================================
extern "C" void kernel_launch(void* const* d_in, const int* in_sizes, int n_in,
                              void* d_out, int out_size)
{
    const float* x  = (const float*)d_in[0];
    const float* sx = (const float*)d_in[1];
    const float* sa = (const float*)d_in[2];
    const float* sb = (const float*)d_in[3];
    const float* sp = (const float*)d_in[4];
    const float* td = (const float*)d_in[5];
    const float* tf = (const float*)d_in[6];
    const float* km = (const float*)d_in[7];
    const float* vm = (const float*)d_in[8];
    const float* rm = (const float*)d_in[9];
    const float* Wk = (const float*)d_in[10];
    const float* Wv = (const float*)d_in[11];
    const float* Wr = (const float*)d_in[12];
    const float* Wo = (const float*)d_in[13];
    float* out = (float*)d_out;
    const int nslots = (int)((size_t)out_size / BH_);

    cudaFuncSetAttribute(hgemm_kernel,
                         cudaFuncAttributeMaxDynamicSharedMemorySize, GSMEM);

    // 1) Fused prep: weight transpose+convert AND token-shift mixing
    prep_kernel<<<WSPLIT_BLOCKS + MIX_BLOCKS, 256>>>(
        Wk, Wv, Wr, Wo, (const float4*)x, (const float4*)sx, km, vm, rm,
        (float4*)(out + BH_), nslots > 1 ? 1 : 0);

    // 2) k, v, r_linear GEMMs (z = 0,1,2)
    hgemm_kernel<<<dim3(HDIM / BN, BDIM / BM, 3), GTHREADS, GSMEM>>>(nullptr, 0);

    // 3) WKV elementwise: aa/bb/p2 outputs + g = sigmoid(r)*wkv
    wkv_kernel<<<(unsigned)(BH_ / 4 / 256), 256>>>(
        (const float4*)sa, (const float4*)sb, (const float4*)sp, td, tf, out, nslots);

    // 4) out = g @ output_weight
    hgemm_kernel<<<dim3(HDIM / BN, BDIM / BM, 1), GTHREADS, GSMEM>>>(out, 1);
}

// round 17
// speedup vs baseline: 1.0375x; 1.0375x over previous
#include <cuda_runtime.h>
#include <cuda_fp16.h>
#include <cstdint>
#include <cstddef>

// ============================================================================
// Problem constants
// ============================================================================
#define HDIM 4096
#define BDIM 4096
static constexpr size_t BH_ = (size_t)HDIM * (size_t)BDIM;   // 16777216

// ============================================================================
// Device scratch (__device__ globals; allocation is forbidden).
//   g_act slots: 0=xk 1=xv 2=xr 3=g(r*wkv)     (fp16, [B,H] K-major)
//   g_wt  slots: 0=Wk^T 1=Wv^T 2=Wr^T 3=Wo^T   (fp16, [N,K] K-major)
//   g_lin slots: 0=k 1=v 2=r_linear            (fp32 [B,H])
// ============================================================================
__device__ __align__(128) __half g_act[4 * BH_];
__device__ __align__(128) __half g_wt[4 * BH_];
__device__ __align__(128) float  g_lin[3 * BH_];

__device__ __forceinline__ uint32_t smem_u32(const void* p) {
    uint32_t a;
    asm("{ .reg .u64 t; cvta.to.shared.u64 t, %1; cvt.u32.u64 %0, t; }"
        : "=r"(a) : "l"(p));
    return a;
}

#define SWZ(o) ((o) ^ (((o) >> 3) & 0x70))

#define CP_ASYNC16(sa, ga)                                                     \
    asm volatile("cp.async.cg.shared.global [%0], [%1], 16;"                   \
                 :: "r"(sa), "l"(ga))

#define MBAR_INIT(addr, cnt)                                                   \
    asm volatile("mbarrier.init.shared.b64 [%0], %1;"                          \
                 :: "r"(addr), "r"(cnt) : "memory")
#define MBAR_ARRIVE(addr)                                                      \
    asm volatile("mbarrier.arrive.shared.b64 _, [%0];"                         \
                 :: "r"(addr) : "memory")
#define CPASYNC_MBAR_ARRIVE(addr)                                              \
    asm volatile("cp.async.mbarrier.arrive.noinc.shared.b64 [%0];"             \
                 :: "r"(addr) : "memory")

#define MBAR_WAIT(addr, ph) do {                                               \
    uint32_t _m = (uint32_t)(addr), _p = (uint32_t)(ph), _d;                   \
    asm volatile(                                                              \
        "{\n\t.reg .pred p;\n\t"                                               \
        "mbarrier.try_wait.parity.acquire.cta.shared::cta.b64 p, [%1], %2;\n\t"\
        "selp.b32 %0, 1, 0, p;\n\t}"                                           \
        : "=r"(_d) : "r"(_m), "r"(_p) : "memory");                             \
    if (!_d) {                                                                 \
        asm volatile(                                                          \
            "{\n\t.reg .pred P1;\n\t"                                          \
            "WL%=:\n\t"                                                        \
            "mbarrier.try_wait.parity.acquire.cta.shared::cta.b64 P1, [%0], %1, 0x989680;\n\t" \
            "@P1 bra.uni WD%=;\n\t"                                            \
            "bra.uni WL%=;\n\t"                                                \
            "WD%=:\n\t}"                                                       \
            :: "r"(_m), "r"(_p) : "memory");                                   \
    }                                                                          \
} while (0)

#define LDSM_X4(r0, r1, r2, r3, addr)                                          \
    asm volatile("ldmatrix.sync.aligned.m8n8.x4.shared.b16 {%0,%1,%2,%3}, [%4];" \
                 : "=r"(r0), "=r"(r1), "=r"(r2), "=r"(r3) : "r"(addr))

#define MMA16816(c, a, b0, b1)                                                 \
    asm volatile("mma.sync.aligned.m16n8k16.row.col.f32.f16.f16.f32 "          \
                 "{%0,%1,%2,%3}, {%4,%5,%6,%7}, {%8,%9}, {%0,%1,%2,%3};"       \
                 : "+f"((c)[0]), "+f"((c)[1]), "+f"((c)[2]), "+f"((c)[3])      \
                 : "r"((a)[0]), "r"((a)[1]), "r"((a)[2]), "r"((a)[3]),         \
                   "r"(b0), "r"(b1))

// ============================================================================
// HGEMM: C[M,N] = A[M,K] @ B^T, B stored [N,K] K-major, fp16 in / fp32 out.
// CTA tile 128x128, BK=64, 3-stage cp.async, 4 warps, warp tile 64x64, occ 2.
// mbarrier-phased producer/consumer pipeline (measured best: r7 = 1560.6us).
//   full[s]:  count=128, signalled by cp.async.mbarrier.arrive.noinc
//   empty[s]: count=128, each thread arrives after its chunk compute
// ============================================================================
#define BM 128
#define BN 128
#define BK 64
#define GTHREADS 128
#define NKITERS (HDIM / BK)                 // 64
#define STAGE_BYTES ((BM + BN) * 128)       // 32768
#define SM_B_OFF (BM * 128)                 // 16384
#define SM_TILE0 1024
#define GSMEM (SM_TILE0 + 3 * STAGE_BYTES)  // 99328

__global__ void __launch_bounds__(GTHREADS, 2)
hgemm_kernel(float* __restrict__ Cout, int mode)
{
    extern __shared__ char smem[];
    const uint32_t sb = smem_u32(smem);
    const int tid = threadIdx.x;
    const int wid = tid >> 5;
    const int lane = tid & 31;

    const int z = (mode == 0) ? (int)blockIdx.z : 3;
    const __half* __restrict__ A = g_act + (size_t)z * BH_;
    const __half* __restrict__ Bw = g_wt + (size_t)z * BH_;
    float* __restrict__ C = (mode == 0) ? (g_lin + (size_t)z * BH_) : Cout;

    // ---- CTA swizzle: 16-wide x-groups (better L2 reuse per wave) ----
    const int bidlin = (int)(blockIdx.x + gridDim.x * blockIdx.y);
    const int per = 16 * (int)gridDim.y;
    const int grp = bidlin / per;
    const int rem = bidlin - grp * per;
    const int m0 = (rem / 16) * BM;
    const int n0 = (grp * 16 + (rem % 16)) * BN;

    // ---- mbarrier init: full[s] at sb+16s, empty[s] at sb+16s+8 ----
    if (tid == 0) {
        #pragma unroll
        for (int s = 0; s < 3; s++) {
            MBAR_INIT(sb + s * 16, GTHREADS);
            MBAR_INIT(sb + s * 16 + 8, GTHREADS);
        }
    }
    __syncthreads();

    // ---- cp.async bases: thread covers chunk (tid + c*128), c = 0..7.
    // +128 chunks = +16 rows = +16*HDIM gmem, +2048B smem (SWZ invariant) ----
    const int lrow = tid >> 3, lcol = tid & 7;
    const __half* gAb = A + (size_t)(m0 + lrow) * HDIM + lcol * 8;
    const __half* gBb = Bw + (size_t)(n0 + lrow) * HDIM + lcol * 8;
    const uint32_t soff = SWZ((uint32_t)(lrow * 128 + lcol * 16));
    const uint32_t sAb = sb + SM_TILE0 + soff;
    const uint32_t sBb = sb + SM_TILE0 + SM_B_OFF + soff;

    #define LOAD_STAGE(slot, kc) do {                                          \
        uint32_t off = (uint32_t)(slot) * STAGE_BYTES;                         \
        size_t ko = (size_t)(kc) * BK;                                         \
        _Pragma("unroll")                                                      \
        for (int c = 0; c < 8; c++)                                            \
            CP_ASYNC16(sAb + off + c * 2048, gAb + ko + (size_t)c * 16 * HDIM);\
        _Pragma("unroll")                                                      \
        for (int c = 0; c < 8; c++)                                            \
            CP_ASYNC16(sBb + off + c * 2048, gBb + ko + (size_t)c * 16 * HDIM);\
    } while (0)

    // ---- warp tiling: 2x2 warps, each 64x64 ----
    const int wm = (wid & 1) * 64;
    const int wn = (wid >> 1) * 64;
    const uint32_t xorv = (uint32_t)((lane & 7) << 4);
    const uint32_t bcol0 = (uint32_t)((lane >> 4) << 4);
    uint32_t rowAoff[4], rowBoff[4];
    #pragma unroll
    for (int mt = 0; mt < 4; mt++)
        rowAoff[mt] = (uint32_t)(SM_TILE0 + (wm + (lane & 15) + mt * 16) * 128);
    #pragma unroll
    for (int nt2 = 0; nt2 < 4; nt2++)
        rowBoff[nt2] = (uint32_t)(SM_TILE0 + SM_B_OFF + (wn + nt2 * 16 + (lane & 15)) * 128);

    float acc[4][8][4];
    #pragma unroll
    for (int mt = 0; mt < 4; mt++)
        #pragma unroll
        for (int nt = 0; nt < 8; nt++)
            #pragma unroll
            for (int e = 0; e < 4; e++) acc[mt][nt][e] = 0.0f;

    uint32_t af[2][4][4], bf[2][4][4];

    #define LOADFRAG(buf, sbase_, ks_) do {                                    \
        const uint32_t bc = ((uint32_t)((ks_) * 32) + bcol0) ^ xorv;           \
        _Pragma("unroll")                                                      \
        for (int mt = 0; mt < 4; mt++)                                         \
            LDSM_X4(af[buf][mt][0], af[buf][mt][1], af[buf][mt][2],            \
                    af[buf][mt][3], (sbase_) + rowAoff[mt] + bc);              \
        _Pragma("unroll")                                                      \
        for (int nt2 = 0; nt2 < 4; nt2++)                                      \
            LDSM_X4(bf[buf][nt2][0], bf[buf][nt2][1], bf[buf][nt2][2],         \
                    bf[buf][nt2][3], (sbase_) + rowBoff[nt2] + bc);            \
    } while (0)

    // ---- prologue: fill stages 0 and 1 (first use of slots — no empty wait)
    LOAD_STAGE(0, 0);
    CPASYNC_MBAR_ARRIVE(sb + 0 * 16);
    LOAD_STAGE(1, 1);
    CPASYNC_MBAR_ARRIVE(sb + 1 * 16);

    for (int kc = 0; kc < NKITERS; kc++) {
        const int s = kc - (kc / 3) * 3;
        // ---- produce chunk kc+2 into slot (kc+2)%3 ----
        const int t = kc + 2;
        if (t < NKITERS) {
            const int s2 = t - (t / 3) * 3;
            if (t >= 3) {
                // wait for all warps to have consumed chunk t-3 from slot s2
                MBAR_WAIT(sb + s2 * 16 + 8, ((t - 3) / 3) & 1);
            }
            LOAD_STAGE(s2, t);
            CPASYNC_MBAR_ARRIVE(sb + s2 * 16);
        }
        // ---- consume chunk kc from slot s ----
        MBAR_WAIT(sb + s * 16, (kc / 3) & 1);

        const uint32_t sbase = sb + (uint32_t)s * STAGE_BYTES;
        LOADFRAG(0, sbase, 0);
        #pragma unroll
        for (int ks = 0; ks < 4; ks++) {
            const int cur = ks & 1;
            if (ks < 3) LOADFRAG(cur ^ 1, sbase, ks + 1);
            #pragma unroll
            for (int mt = 0; mt < 4; mt++) {
                #pragma unroll
                for (int nt = 0; nt < 8; nt++) {
                    uint32_t b0 = (nt & 1) ? bf[cur][nt >> 1][1] : bf[cur][nt >> 1][0];
                    uint32_t b1 = (nt & 1) ? bf[cur][nt >> 1][3] : bf[cur][nt >> 1][2];
                    MMA16816(acc[mt][nt], af[cur][mt], b0, b1);
                }
            }
        }
        MBAR_ARRIVE(sb + s * 16 + 8);    // slot s free for reuse
    }

    // ---- epilogue: fp32 accum -> C ----
    const int gr = lane >> 2;           // row group 0..7
    const int gc = (lane & 3) * 2;      // col pair
    #pragma unroll
    for (int mt = 0; mt < 4; mt++) {
        #pragma unroll
        for (int nt = 0; nt < 8; nt++) {
            int row = m0 + wm + mt * 16 + gr;
            int col = n0 + wn + nt * 8 + gc;
            float2 v0 = make_float2(acc[mt][nt][0], acc[mt][nt][1]);
            float2 v1 = make_float2(acc[mt][nt][2], acc[mt][nt][3]);
            *(float2*)(C + (size_t)row * HDIM + col) = v0;
            *(float2*)(C + (size_t)(row + 8) * HDIM + col) = v1;
        }
    }
    #undef LOAD_STAGE
    #undef LOADFRAG
}

// ============================================================================
// Fused prep kernel: weight transpose+fp16 convert AND token-shift mixing in
// one launch so the two bandwidth-bound passes overlap on the device.
//   blocks [0, WSPLIT_BLOCKS): wsplit 32x32 transpose tiles
//   blocks [WSPLIT_BLOCKS, +MIX_BLOCKS): mix (256 elems each, float4 lanes)
// ============================================================================
#define WSPLIT_BLOCKS (4 * (HDIM / 32) * (HDIM / 32))   // 65536
#define MIX_BLOCKS ((int)(BH_ / 4 / 256))               // 16384

__device__ __forceinline__ void half_store4(int slot, size_t i,
                                            float a0, float a1, float a2, float a3)
{
    union { __half h[4]; uint2 u; } u;
    u.h[0] = __float2half_rn(a0);
    u.h[1] = __float2half_rn(a1);
    u.h[2] = __float2half_rn(a2);
    u.h[3] = __float2half_rn(a3);
    ((uint2*)g_act)[(size_t)slot * (BH_ / 4) + i] = u.u;
}

__global__ void prep_kernel(const float* __restrict__ W0, const float* __restrict__ W1,
                            const float* __restrict__ W2, const float* __restrict__ W3,
                            const float4* __restrict__ x, const float4* __restrict__ sx,
                            const float* __restrict__ km, const float* __restrict__ vm,
                            const float* __restrict__ rm, float4* __restrict__ out_x,
                            int do_copy)
{
    __shared__ float tile[32][33];
    int b = (int)blockIdx.x;
    if (b < WSPLIT_BLOCKS) {
        // ---- weight transpose + convert ----
        const int z = b >> 14;                   // / (128*128)
        const int r = b & 16383;
        const int n0 = (r & 127) * 32;
        const int k0 = (r >> 7) * 32;
        const float* W = (z == 0) ? W0 : (z == 1) ? W1 : (z == 2) ? W2 : W3;
        const int tx = threadIdx.x & 31, ty = threadIdx.x >> 5;   // 32 x 8

        #pragma unroll
        for (int i = 0; i < 4; i++)
            tile[ty + 8 * i][tx] = W[(size_t)(k0 + ty + 8 * i) * HDIM + (n0 + tx)];
        __syncthreads();

        const size_t base = (size_t)z * BH_;
        #pragma unroll
        for (int i = 0; i < 4; i++) {
            float v = tile[tx][ty + 8 * i];
            g_wt[base + (size_t)(n0 + ty + 8 * i) * HDIM + (k0 + tx)] = __float2half_rn(v);
        }
    } else {
        // ---- token-shift mixing ----
        b -= WSPLIT_BLOCKS;
        size_t i = (size_t)b * 256 + threadIdx.x;    // over BH/4
        float4 xv = x[i], sv = sx[i];
        int h = (int)((i * 4) & (HDIM - 1));
        float4 kmv = *(const float4*)(km + h);
        float4 vmv = *(const float4*)(vm + h);
        float4 rmv = *(const float4*)(rm + h);
        if (do_copy) out_x[i] = xv;
        half_store4(0, i,
            fmaf(kmv.x, xv.x - sv.x, sv.x), fmaf(kmv.y, xv.y - sv.y, sv.y),
            fmaf(kmv.z, xv.z - sv.z, sv.z), fmaf(kmv.w, xv.w - sv.w, sv.w));
        half_store4(1, i,
            fmaf(vmv.x, xv.x - sv.x, sv.x), fmaf(vmv.y, xv.y - sv.y, sv.y),
            fmaf(vmv.z, xv.z - sv.z, sv.z), fmaf(vmv.w, xv.w - sv.w, sv.w));
        half_store4(2, i,
            fmaf(rmv.x, xv.x - sv.x, sv.x), fmaf(rmv.y, xv.y - sv.y, sv.y),
            fmaf(rmv.z, xv.z - sv.z, sv.z), fmaf(rmv.w, xv.w - sv.w, sv.w));
    }
}

// ============================================================================
// WKV elementwise
// ============================================================================
__device__ __forceinline__ void wkv_comp(float k, float v, float rl,
                                         float A, float Bv, float P,
                                         float tfv, float tdv,
                                         float& aa, float& bb, float& p2o, float& g)
{
    float r = 1.0f / (1.0f + expf(-rl));
    float w = k + tfv;
    float p = fmaxf(P, w);
    float e1 = expf(P - p), e2 = expf(w - p);
    float wkv = (e1 * A + e2 * v) / (e1 * Bv + e2);
    float w2 = P + tdv;
    p2o = fmaxf(w2, k);
    float ea = expf(w2 - p2o), eb = expf(k - p2o);
    aa = ea * A + eb * v;
    bb = ea * Bv + eb;
    g = r * wkv;
}

__global__ void wkv_kernel(const float4* __restrict__ sa, const float4* __restrict__ sb,
                           const float4* __restrict__ sp, const float* __restrict__ td,
                           const float* __restrict__ tf, float* __restrict__ out,
                           int nslots)
{
    size_t i = (size_t)blockIdx.x * blockDim.x + threadIdx.x;    // over BH/4
    int h = (int)((i * 4) & (HDIM - 1));
    const float4* lin = (const float4*)g_lin;
    float4 k4 = lin[i];
    float4 v4 = lin[BH_ / 4 + i];
    float4 r4 = lin[2 * (BH_ / 4) + i];
    float4 sa4 = sa[i], sb4 = sb[i], sp4 = sp[i];
    float4 tf4 = *(const float4*)(tf + h);
    float4 td4 = *(const float4*)(td + h);

    float4 aa4, bb4, p24;
    float g0, g1, g2, g3;
    wkv_comp(k4.x, v4.x, r4.x, sa4.x, sb4.x, sp4.x, tf4.x, td4.x, aa4.x, bb4.x, p24.x, g0);
    wkv_comp(k4.y, v4.y, r4.y, sa4.y, sb4.y, sp4.y, tf4.y, td4.y, aa4.y, bb4.y, p24.y, g1);
    wkv_comp(k4.z, v4.z, r4.z, sa4.z, sb4.z, sp4.z, tf4.z, td4.z, aa4.z, bb4.z, p24.z, g2);
    wkv_comp(k4.w, v4.w, r4.w, sa4.w, sb4.w, sp4.w, tf4.w, td4.w, aa4.w, bb4.w, p24.w, g3);

    if (nslots > 2) ((float4*)(out + 2 * BH_))[i] = aa4;
    if (nslots > 3) ((float4*)(out + 3 * BH_))[i] = bb4;
    if (nslots > 4) ((float4*)(out + 4 * BH_))[i] = p24;
    half_store4(3, i, g0, g1, g2, g3);
}

// ============================================================================
// Launch (serial schedule — every overlap/co-tenancy variant measured slower)
// ============================================================================
extern "C" void kernel_launch(void* const* d_in, const int* in_sizes, int n_in,
                              void* d_out, int out_size)
{
    const float* x  = (const float*)d_in[0];
    const float* sx = (const float*)d_in[1];
    const float* sa = (const float*)d_in[2];
    const float* sb = (const float*)d_in[3];
    const float* sp = (const float*)d_in[4];
    const float* td = (const float*)d_in[5];
    const float* tf = (const float*)d_in[6];
    const float* km = (const float*)d_in[7];
    const float* vm = (const float*)d_in[8];
    const float* rm = (const float*)d_in[9];
    const float* Wk = (const float*)d_in[10];
    const float* Wv = (const float*)d_in[11];
    const float* Wr = (const float*)d_in[12];
    const float* Wo = (const float*)d_in[13];
    float* out = (float*)d_out;
    const int nslots = (int)((size_t)out_size / BH_);

    cudaFuncSetAttribute(hgemm_kernel,
                         cudaFuncAttributeMaxDynamicSharedMemorySize, GSMEM);

    // 1) Fused prep: weight transpose+convert AND token-shift mixing
    prep_kernel<<<WSPLIT_BLOCKS + MIX_BLOCKS, 256>>>(
        Wk, Wv, Wr, Wo, (const float4*)x, (const float4*)sx, km, vm, rm,
        (float4*)(out + BH_), nslots > 1 ? 1 : 0);

    // 2) k, v, r_linear GEMMs (z = 0,1,2)
    hgemm_kernel<<<dim3(HDIM / BN, BDIM / BM, 3), GTHREADS, GSMEM>>>(nullptr, 0);

    // 3) WKV elementwise: aa/bb/p2 outputs + g = sigmoid(r)*wkv
    wkv_kernel<<<(unsigned)(BH_ / 4 / 256), 256>>>(
        (const float4*)sa, (const float4*)sb, (const float4*)sp, td, tf, out, nslots);

    // 4) out = g @ output_weight
    hgemm_kernel<<<dim3(HDIM / BN, BDIM / BM, 1), GTHREADS, GSMEM>>>(out, 1);
}